// round 12
// baseline (speedup 1.0000x reference)
#include <cuda_runtime.h>
#include <math.h>
#include <stdint.h>

// Problem constants
#define S_LEN 2048
#define HID   4096
#define NH    32
#define NKV   8
#define DH    128
#define WIN   1024

// Scratch (device globals — no cudaMalloc allowed)
__device__ float g_q[S_LEN * NH * DH];      // 32 MB
__device__ float g_k[S_LEN * NKV * DH];     //  8 MB
__device__ float g_v[S_LEN * NKV * DH];     //  8 MB
__device__ float g_attn[S_LEN * NH * DH];   // 32 MB

// ---------------------------------------------------------------------------
// SGEMM: C[M,N] = A[M,K] @ B[K,N] (+ optional bias[N])
// 128x128 block tile, K-tile 8, 256 threads, 8x8 per thread.
// A row-major, B row-major. M,N,K multiples of 128/128/8 (true here).
// ---------------------------------------------------------------------------
__global__ void __launch_bounds__(256, 2)
sgemm_bias(const float* __restrict__ A, const float* __restrict__ B,
           const float* __restrict__ bias, float* __restrict__ C,
           int M, int N, int K)
{
    __shared__ float As[8][128];   // [k][m] (transposed)
    __shared__ float Bs[8][128];   // [k][n]

    const int tid = threadIdx.x;
    const int bm  = blockIdx.y * 128;
    const int bn  = blockIdx.x * 128;
    const int ty  = tid >> 4;      // 0..15 -> rows ty*8..ty*8+7
    const int tx  = tid & 15;      // 0..15 -> cols tx*8..tx*8+7

    // global load mapping
    const int arow = tid >> 1;            // 0..127
    const int acol = (tid & 1) * 4;       // 0 or 4
    const int brow = tid >> 5;            // 0..7
    const int bcol = (tid & 31) * 4;      // 0..124

    float acc[8][8];
    #pragma unroll
    for (int i = 0; i < 8; i++) {
        #pragma unroll
        for (int j = 0; j < 8; j++) acc[i][j] = 0.0f;
    }

    const float* Aptr = A + (size_t)(bm + arow) * K + acol;
    const float* Bptr = B + (size_t)brow * N + bn + bcol;

    for (int k0 = 0; k0 < K; k0 += 8) {
        float4 a = *(const float4*)(Aptr + k0);
        float4 b = *(const float4*)(Bptr + (size_t)k0 * N);
        As[acol + 0][arow] = a.x;
        As[acol + 1][arow] = a.y;
        As[acol + 2][arow] = a.z;
        As[acol + 3][arow] = a.w;
        *(float4*)&Bs[brow][bcol] = b;
        __syncthreads();

        #pragma unroll
        for (int kk = 0; kk < 8; kk++) {
            float af[8], bf[8];
            *(float4*)(af)     = *(const float4*)&As[kk][ty * 8];
            *(float4*)(af + 4) = *(const float4*)&As[kk][ty * 8 + 4];
            *(float4*)(bf)     = *(const float4*)&Bs[kk][tx * 8];
            *(float4*)(bf + 4) = *(const float4*)&Bs[kk][tx * 8 + 4];
            #pragma unroll
            for (int i = 0; i < 8; i++) {
                #pragma unroll
                for (int j = 0; j < 8; j++)
                    acc[i][j] = fmaf(af[i], bf[j], acc[i][j]);
            }
        }
        __syncthreads();
    }

    float bvals[8];
    if (bias != nullptr) {
        *(float4*)(bvals)     = *(const float4*)(bias + bn + tx * 8);
        *(float4*)(bvals + 4) = *(const float4*)(bias + bn + tx * 8 + 4);
    } else {
        #pragma unroll
        for (int j = 0; j < 8; j++) bvals[j] = 0.0f;
    }

    #pragma unroll
    for (int i = 0; i < 8; i++) {
        float* cp = C + (size_t)(bm + ty * 8 + i) * N + bn + tx * 8;
        float4 r0, r1;
        r0.x = acc[i][0] + bvals[0]; r0.y = acc[i][1] + bvals[1];
        r0.z = acc[i][2] + bvals[2]; r0.w = acc[i][3] + bvals[3];
        r1.x = acc[i][4] + bvals[4]; r1.y = acc[i][5] + bvals[5];
        r1.z = acc[i][6] + bvals[6]; r1.w = acc[i][7] + bvals[7];
        *(float4*)(cp)     = r0;
        *(float4*)(cp + 4) = r1;
    }
}

// ---------------------------------------------------------------------------
// RoPE (neox split-halves), in place. x layout: [s][nh*128].
// inv_freq via double pow rounded to f32 to track the reference's fp32 value.
// ---------------------------------------------------------------------------
__global__ void rope_kernel(float* __restrict__ x, const int* __restrict__ pos, int nh)
{
    int idx = blockIdx.x * blockDim.x + threadIdx.x;
    int total = S_LEN * nh * 64;
    if (idx >= total) return;
    int dh = idx & 63;
    int t  = idx >> 6;
    int h  = t % nh;
    int s  = t / nh;

    float invf = (float)pow(1000000.0, -(double)dh / 64.0);
    float p    = (float)pos[s];
    float ang  = p * invf;
    float c = cosf(ang);
    float sn = sinf(ang);

    float* base = x + ((size_t)s * nh + h) * DH;
    float x1 = base[dh];
    float x2 = base[dh + 64];
    base[dh]      = x1 * c - x2 * sn;
    base[dh + 64] = x2 * c + x1 * sn;
}

// ---------------------------------------------------------------------------
// Flash attention, fp32, sliding window + causal + sink.
// Block = (q-tile of 64 rows, one head). 256 threads.
// Thread (ty = tid/16, tx = tid%16): owns q-rows ty*4..ty*4+3;
//   score phase: k-cols tx*4..tx*4+3; PV phase: d-cols tx*8..tx*8+7.
// Sink folded into online-softmax init: m0 = sink[h], l0 = 1, O0 = 0.
// Smem: Qst[128][64] (d-major, scaled), Kst[128][64], Vs[64][128], Ss[64][64].
// ---------------------------------------------------------------------------
#define ATTN_SMEM_FLOATS (128*64 + 128*64 + 64*128 + 64*64)

__global__ void __launch_bounds__(256, 1)
attn_kernel(const float* __restrict__ q, const float* __restrict__ k,
            const float* __restrict__ v, const float* __restrict__ sink,
            float* __restrict__ out)
{
    extern __shared__ float sm[];
    float* Qst = sm;                         // [128][64]
    float* Kst = sm + 128 * 64;              // [128][64]
    float* Vs  = sm + 2 * 128 * 64;          // [64][128]
    float* Ss  = sm + 2 * 128 * 64 + 64*128; // [64][64]

    const int tid = threadIdx.x;
    const int ty  = tid >> 4;
    const int tx  = tid & 15;
    const int q0  = blockIdx.x * 64;
    const int h   = blockIdx.y;
    const int hk  = h >> 2;   // GQA group = 4
    const float scale = 0.08838834764831845f;  // 1/sqrt(128)

    // Load Q tile, transposed + pre-scaled
    #pragma unroll
    for (int i = 0; i < 8; i++) {
        int e = tid + 256 * i;
        int row = e >> 5;
        int c4  = (e & 31) * 4;
        float4 a = *(const float4*)(q + (size_t)(q0 + row) * (NH * DH) + h * DH + c4);
        Qst[(c4 + 0) * 64 + row] = a.x * scale;
        Qst[(c4 + 1) * 64 + row] = a.y * scale;
        Qst[(c4 + 2) * 64 + row] = a.z * scale;
        Qst[(c4 + 3) * 64 + row] = a.w * scale;
    }

    float m[4], l[4], o[4][8];
    float snk = sink[h];
    #pragma unroll
    for (int i = 0; i < 4; i++) {
        m[i] = snk;
        l[i] = 1.0f;
        #pragma unroll
        for (int j = 0; j < 8; j++) o[i][j] = 0.0f;
    }

    const int kt0 = (q0 >= WIN) ? ((q0 - (WIN - 1)) >> 6) : 0;
    const int kt1 = q0 >> 6;

    for (int kt = kt0; kt <= kt1; kt++) {
        int j0 = kt * 64;
        __syncthreads();  // previous tile's Kst/Vs/Ss fully consumed

        // Load K (transposed) and V tiles for kv head hk
        #pragma unroll
        for (int i = 0; i < 8; i++) {
            int e = tid + 256 * i;
            int row = e >> 5;
            int c4  = (e & 31) * 4;
            float4 kk4 = *(const float4*)(k + (size_t)(j0 + row) * (NKV * DH) + hk * DH + c4);
            Kst[(c4 + 0) * 64 + row] = kk4.x;
            Kst[(c4 + 1) * 64 + row] = kk4.y;
            Kst[(c4 + 2) * 64 + row] = kk4.z;
            Kst[(c4 + 3) * 64 + row] = kk4.w;
            float4 vv = *(const float4*)(v + (size_t)(j0 + row) * (NKV * DH) + hk * DH + c4);
            *(float4*)&Vs[row * 128 + c4] = vv;
        }
        __syncthreads();

        // Scores: s4[ii][jj] = Q[ty*4+ii] . K[tx*4+jj]  (Q pre-scaled)
        float s4[4][4];
        #pragma unroll
        for (int ii = 0; ii < 4; ii++) {
            #pragma unroll
            for (int jj = 0; jj < 4; jj++) s4[ii][jj] = 0.0f;
        }
        #pragma unroll 8
        for (int d = 0; d < 128; d++) {
            float4 a = *(const float4*)&Qst[d * 64 + ty * 4];
            float4 b = *(const float4*)&Kst[d * 64 + tx * 4];
            s4[0][0] = fmaf(a.x, b.x, s4[0][0]); s4[0][1] = fmaf(a.x, b.y, s4[0][1]);
            s4[0][2] = fmaf(a.x, b.z, s4[0][2]); s4[0][3] = fmaf(a.x, b.w, s4[0][3]);
            s4[1][0] = fmaf(a.y, b.x, s4[1][0]); s4[1][1] = fmaf(a.y, b.y, s4[1][1]);
            s4[1][2] = fmaf(a.y, b.z, s4[1][2]); s4[1][3] = fmaf(a.y, b.w, s4[1][3]);
            s4[2][0] = fmaf(a.z, b.x, s4[2][0]); s4[2][1] = fmaf(a.z, b.y, s4[2][1]);
            s4[2][2] = fmaf(a.z, b.z, s4[2][2]); s4[2][3] = fmaf(a.z, b.w, s4[2][3]);
            s4[3][0] = fmaf(a.w, b.x, s4[3][0]); s4[3][1] = fmaf(a.w, b.y, s4[3][1]);
            s4[3][2] = fmaf(a.w, b.z, s4[3][2]); s4[3][3] = fmaf(a.w, b.w, s4[3][3]);
        }

        // Mask + online softmax (row stats across the 16 tx lanes via shfl)
        #pragma unroll
        for (int ii = 0; ii < 4; ii++) {
            int gi = q0 + ty * 4 + ii;
            #pragma unroll
            for (int jj = 0; jj < 4; jj++) {
                int gj = j0 + tx * 4 + jj;
                if (gj > gi || gj <= gi - WIN) s4[ii][jj] = -1e30f;
            }
            float rmax = fmaxf(fmaxf(s4[ii][0], s4[ii][1]), fmaxf(s4[ii][2], s4[ii][3]));
            #pragma unroll
            for (int off = 8; off >= 1; off >>= 1)
                rmax = fmaxf(rmax, __shfl_xor_sync(0xffffffffu, rmax, off));
            float mn = fmaxf(m[ii], rmax);
            float sc = __expf(m[ii] - mn);
            float rs = 0.0f;
            #pragma unroll
            for (int jj = 0; jj < 4; jj++) {
                float p = __expf(s4[ii][jj] - mn);
                s4[ii][jj] = p;
                rs += p;
            }
            #pragma unroll
            for (int off = 8; off >= 1; off >>= 1)
                rs += __shfl_xor_sync(0xffffffffu, rs, off);
            l[ii] = l[ii] * sc + rs;
            m[ii] = mn;
            #pragma unroll
            for (int d = 0; d < 8; d++) o[ii][d] *= sc;
            *(float4*)&Ss[(ty * 4 + ii) * 64 + tx * 4] = *(float4*)s4[ii];
        }
        __syncthreads();

        // PV: o[ii][0..7] += sum_j P[row][j] * V[j][tx*8..tx*8+7]
        #pragma unroll 4
        for (int j = 0; j < 64; j++) {
            float4 v0 = *(const float4*)&Vs[j * 128 + tx * 8];
            float4 v1 = *(const float4*)&Vs[j * 128 + tx * 8 + 4];
            #pragma unroll
            for (int ii = 0; ii < 4; ii++) {
                float p = Ss[(ty * 4 + ii) * 64 + j];
                o[ii][0] = fmaf(p, v0.x, o[ii][0]);
                o[ii][1] = fmaf(p, v0.y, o[ii][1]);
                o[ii][2] = fmaf(p, v0.z, o[ii][2]);
                o[ii][3] = fmaf(p, v0.w, o[ii][3]);
                o[ii][4] = fmaf(p, v1.x, o[ii][4]);
                o[ii][5] = fmaf(p, v1.y, o[ii][5]);
                o[ii][6] = fmaf(p, v1.z, o[ii][6]);
                o[ii][7] = fmaf(p, v1.w, o[ii][7]);
            }
        }
    }

    // Normalize and write [s][h*128 + d]
    #pragma unroll
    for (int ii = 0; ii < 4; ii++) {
        float inv = 1.0f / l[ii];
        float* op = out + (size_t)(q0 + ty * 4 + ii) * (NH * DH) + h * DH + tx * 8;
        float4 r0, r1;
        r0.x = o[ii][0] * inv; r0.y = o[ii][1] * inv;
        r0.z = o[ii][2] * inv; r0.w = o[ii][3] * inv;
        r1.x = o[ii][4] * inv; r1.y = o[ii][5] * inv;
        r1.z = o[ii][6] * inv; r1.w = o[ii][7] * inv;
        *(float4*)(op)     = r0;
        *(float4*)(op + 4) = r1;
    }
}

// ---------------------------------------------------------------------------
// Launch: QKV GEMMs -> RoPE(q,k) -> attention -> O GEMM
// Inputs (metadata order): positions, hidden_states, Wq, bq, Wk, bk, Wv, bv, Wo, sink
// ---------------------------------------------------------------------------
extern "C" void kernel_launch(void* const* d_in, const int* in_sizes, int n_in,
                              void* d_out, int out_size)
{
    const int*   positions = (const int*)  d_in[0];
    const float* hidden    = (const float*)d_in[1];
    const float* Wq        = (const float*)d_in[2];
    const float* bq        = (const float*)d_in[3];
    const float* Wk        = (const float*)d_in[4];
    const float* bk        = (const float*)d_in[5];
    const float* Wv        = (const float*)d_in[6];
    const float* bv        = (const float*)d_in[7];
    const float* Wo        = (const float*)d_in[8];
    const float* sink      = (const float*)d_in[9];
    float* out = (float*)d_out;

    float *qp, *kp, *vp, *ap;
    cudaGetSymbolAddress((void**)&qp, g_q);
    cudaGetSymbolAddress((void**)&kp, g_k);
    cudaGetSymbolAddress((void**)&vp, g_v);
    cudaGetSymbolAddress((void**)&ap, g_attn);

    dim3 blk(256);

    // QKV projections
    sgemm_bias<<<dim3(HID / 128, S_LEN / 128), blk>>>(hidden, Wq, bq, qp, S_LEN, HID, HID);
    sgemm_bias<<<dim3((NKV * DH) / 128, S_LEN / 128), blk>>>(hidden, Wk, bk, kp, S_LEN, NKV * DH, HID);
    sgemm_bias<<<dim3((NKV * DH) / 128, S_LEN / 128), blk>>>(hidden, Wv, bv, vp, S_LEN, NKV * DH, HID);

    // RoPE on q and k
    rope_kernel<<<(S_LEN * NH  * 64 + 255) / 256, 256>>>(qp, positions, NH);
    rope_kernel<<<(S_LEN * NKV * 64 + 255) / 256, 256>>>(kp, positions, NKV);

    // Attention
    int smem_bytes = ATTN_SMEM_FLOATS * (int)sizeof(float);  // 114688
    cudaFuncSetAttribute(attn_kernel, cudaFuncAttributeMaxDynamicSharedMemorySize, smem_bytes);
    attn_kernel<<<dim3(S_LEN / 64, NH), blk, smem_bytes>>>(qp, kp, vp, sink, ap);

    // Output projection (no bias)
    sgemm_bias<<<dim3(HID / 128, S_LEN / 128), blk>>>(ap, Wo, nullptr, out, S_LEN, HID, HID);
}

// round 13
// speedup vs baseline: 1.0040x; 1.0040x over previous
#include <cuda_runtime.h>
#include <math.h>
#include <stdint.h>

// Problem constants
#define S_LEN 2048
#define HID   4096
#define NH    32
#define NKV   8
#define DH    128
#define WIN   1024

// Scratch (device globals — no cudaMalloc allowed)
__device__ float g_q[S_LEN * NH * DH];      // 32 MB
__device__ float g_k[S_LEN * NKV * DH];     //  8 MB
__device__ float g_v[S_LEN * NKV * DH];     //  8 MB
__device__ float g_attn[S_LEN * NH * DH];   // 32 MB

// ---------------------------------------------------------------------------
// SGEMM: C[M,N] = A[M,K] @ B[K,N] (+ optional bias[N])
// 128x128 block tile, K-tile 8, 256 threads, 8x8 per thread.
// A row-major, B row-major. M,N,K multiples of 128/128/8 (true here).
// ---------------------------------------------------------------------------
__global__ void __launch_bounds__(256, 2)
sgemm_bias(const float* __restrict__ A, const float* __restrict__ B,
           const float* __restrict__ bias, float* __restrict__ C,
           int M, int N, int K)
{
    __shared__ float As[8][128];   // [k][m] (transposed)
    __shared__ float Bs[8][128];   // [k][n]

    const int tid = threadIdx.x;
    const int bm  = blockIdx.y * 128;
    const int bn  = blockIdx.x * 128;
    const int ty  = tid >> 4;      // 0..15 -> rows ty*8..ty*8+7
    const int tx  = tid & 15;      // 0..15 -> cols tx*8..tx*8+7

    // global load mapping
    const int arow = tid >> 1;            // 0..127
    const int acol = (tid & 1) * 4;       // 0 or 4
    const int brow = tid >> 5;            // 0..7
    const int bcol = (tid & 31) * 4;      // 0..124

    float acc[8][8];
    #pragma unroll
    for (int i = 0; i < 8; i++) {
        #pragma unroll
        for (int j = 0; j < 8; j++) acc[i][j] = 0.0f;
    }

    const float* Aptr = A + (size_t)(bm + arow) * K + acol;
    const float* Bptr = B + (size_t)brow * N + bn + bcol;

    for (int k0 = 0; k0 < K; k0 += 8) {
        float4 a = *(const float4*)(Aptr + k0);
        float4 b = *(const float4*)(Bptr + (size_t)k0 * N);
        As[acol + 0][arow] = a.x;
        As[acol + 1][arow] = a.y;
        As[acol + 2][arow] = a.z;
        As[acol + 3][arow] = a.w;
        *(float4*)&Bs[brow][bcol] = b;
        __syncthreads();

        #pragma unroll
        for (int kk = 0; kk < 8; kk++) {
            float af[8], bf[8];
            *(float4*)(af)     = *(const float4*)&As[kk][ty * 8];
            *(float4*)(af + 4) = *(const float4*)&As[kk][ty * 8 + 4];
            *(float4*)(bf)     = *(const float4*)&Bs[kk][tx * 8];
            *(float4*)(bf + 4) = *(const float4*)&Bs[kk][tx * 8 + 4];
            #pragma unroll
            for (int i = 0; i < 8; i++) {
                #pragma unroll
                for (int j = 0; j < 8; j++)
                    acc[i][j] = fmaf(af[i], bf[j], acc[i][j]);
            }
        }
        __syncthreads();
    }

    float bvals[8];
    if (bias != nullptr) {
        *(float4*)(bvals)     = *(const float4*)(bias + bn + tx * 8);
        *(float4*)(bvals + 4) = *(const float4*)(bias + bn + tx * 8 + 4);
    } else {
        #pragma unroll
        for (int j = 0; j < 8; j++) bvals[j] = 0.0f;
    }

    #pragma unroll
    for (int i = 0; i < 8; i++) {
        float* cp = C + (size_t)(bm + ty * 8 + i) * N + bn + tx * 8;
        float4 r0, r1;
        r0.x = acc[i][0] + bvals[0]; r0.y = acc[i][1] + bvals[1];
        r0.z = acc[i][2] + bvals[2]; r0.w = acc[i][3] + bvals[3];
        r1.x = acc[i][4] + bvals[4]; r1.y = acc[i][5] + bvals[5];
        r1.z = acc[i][6] + bvals[6]; r1.w = acc[i][7] + bvals[7];
        *(float4*)(cp)     = r0;
        *(float4*)(cp + 4) = r1;
    }
}

// ---------------------------------------------------------------------------
// RoPE (neox split-halves), in place. x layout: [s][nh*128].
// inv_freq via double pow rounded to f32 to track the reference's fp32 value.
// ---------------------------------------------------------------------------
__global__ void rope_kernel(float* __restrict__ x, const int* __restrict__ pos, int nh)
{
    int idx = blockIdx.x * blockDim.x + threadIdx.x;
    int total = S_LEN * nh * 64;
    if (idx >= total) return;
    int dh = idx & 63;
    int t  = idx >> 6;
    int h  = t % nh;
    int s  = t / nh;

    float invf = (float)pow(1000000.0, -(double)dh / 64.0);
    float p    = (float)pos[s];
    float ang  = p * invf;
    float c = cosf(ang);
    float sn = sinf(ang);

    float* base = x + ((size_t)s * nh + h) * DH;
    float x1 = base[dh];
    float x2 = base[dh + 64];
    base[dh]      = x1 * c - x2 * sn;
    base[dh + 64] = x2 * c + x1 * sn;
}

// ---------------------------------------------------------------------------
// Flash attention, fp32, sliding window + causal + sink.
// Block = (q-tile of 64 rows, one head). 256 threads.
// Thread (ty = tid/16, tx = tid%16): owns q-rows ty*4..ty*4+3;
//   score phase: k-cols tx*4..tx*4+3; PV phase: d-cols tx*8..tx*8+7.
// Sink folded into online-softmax init: m0 = sink[h], l0 = 1, O0 = 0.
// Smem: Qst[128][64] (d-major, scaled), Kst[128][64], Vs[64][128], Ss[64][64].
// ---------------------------------------------------------------------------
#define ATTN_SMEM_FLOATS (128*64 + 128*64 + 64*128 + 64*64)

__global__ void __launch_bounds__(256, 1)
attn_kernel(const float* __restrict__ q, const float* __restrict__ k,
            const float* __restrict__ v, const float* __restrict__ sink,
            float* __restrict__ out)
{
    extern __shared__ float sm[];
    float* Qst = sm;                         // [128][64]
    float* Kst = sm + 128 * 64;              // [128][64]
    float* Vs  = sm + 2 * 128 * 64;          // [64][128]
    float* Ss  = sm + 2 * 128 * 64 + 64*128; // [64][64]

    const int tid = threadIdx.x;
    const int ty  = tid >> 4;
    const int tx  = tid & 15;
    const int q0  = blockIdx.x * 64;
    const int h   = blockIdx.y;
    const int hk  = h >> 2;   // GQA group = 4
    const float scale = 0.08838834764831845f;  // 1/sqrt(128)

    // Load Q tile, transposed + pre-scaled
    #pragma unroll
    for (int i = 0; i < 8; i++) {
        int e = tid + 256 * i;
        int row = e >> 5;
        int c4  = (e & 31) * 4;
        float4 a = *(const float4*)(q + (size_t)(q0 + row) * (NH * DH) + h * DH + c4);
        Qst[(c4 + 0) * 64 + row] = a.x * scale;
        Qst[(c4 + 1) * 64 + row] = a.y * scale;
        Qst[(c4 + 2) * 64 + row] = a.z * scale;
        Qst[(c4 + 3) * 64 + row] = a.w * scale;
    }

    float m[4], l[4], o[4][8];
    float snk = sink[h];
    #pragma unroll
    for (int i = 0; i < 4; i++) {
        m[i] = snk;
        l[i] = 1.0f;
        #pragma unroll
        for (int j = 0; j < 8; j++) o[i][j] = 0.0f;
    }

    const int kt0 = (q0 >= WIN) ? ((q0 - (WIN - 1)) >> 6) : 0;
    const int kt1 = q0 >> 6;

    for (int kt = kt0; kt <= kt1; kt++) {
        int j0 = kt * 64;
        __syncthreads();  // previous tile's Kst/Vs/Ss fully consumed

        // Load K (transposed) and V tiles for kv head hk
        #pragma unroll
        for (int i = 0; i < 8; i++) {
            int e = tid + 256 * i;
            int row = e >> 5;
            int c4  = (e & 31) * 4;
            float4 kk4 = *(const float4*)(k + (size_t)(j0 + row) * (NKV * DH) + hk * DH + c4);
            Kst[(c4 + 0) * 64 + row] = kk4.x;
            Kst[(c4 + 1) * 64 + row] = kk4.y;
            Kst[(c4 + 2) * 64 + row] = kk4.z;
            Kst[(c4 + 3) * 64 + row] = kk4.w;
            float4 vv = *(const float4*)(v + (size_t)(j0 + row) * (NKV * DH) + hk * DH + c4);
            *(float4*)&Vs[row * 128 + c4] = vv;
        }
        __syncthreads();

        // Scores: s4[ii][jj] = Q[ty*4+ii] . K[tx*4+jj]  (Q pre-scaled)
        float s4[4][4];
        #pragma unroll
        for (int ii = 0; ii < 4; ii++) {
            #pragma unroll
            for (int jj = 0; jj < 4; jj++) s4[ii][jj] = 0.0f;
        }
        #pragma unroll 8
        for (int d = 0; d < 128; d++) {
            float4 a = *(const float4*)&Qst[d * 64 + ty * 4];
            float4 b = *(const float4*)&Kst[d * 64 + tx * 4];
            s4[0][0] = fmaf(a.x, b.x, s4[0][0]); s4[0][1] = fmaf(a.x, b.y, s4[0][1]);
            s4[0][2] = fmaf(a.x, b.z, s4[0][2]); s4[0][3] = fmaf(a.x, b.w, s4[0][3]);
            s4[1][0] = fmaf(a.y, b.x, s4[1][0]); s4[1][1] = fmaf(a.y, b.y, s4[1][1]);
            s4[1][2] = fmaf(a.y, b.z, s4[1][2]); s4[1][3] = fmaf(a.y, b.w, s4[1][3]);
            s4[2][0] = fmaf(a.z, b.x, s4[2][0]); s4[2][1] = fmaf(a.z, b.y, s4[2][1]);
            s4[2][2] = fmaf(a.z, b.z, s4[2][2]); s4[2][3] = fmaf(a.z, b.w, s4[2][3]);
            s4[3][0] = fmaf(a.w, b.x, s4[3][0]); s4[3][1] = fmaf(a.w, b.y, s4[3][1]);
            s4[3][2] = fmaf(a.w, b.z, s4[3][2]); s4[3][3] = fmaf(a.w, b.w, s4[3][3]);
        }

        // Mask + online softmax (row stats across the 16 tx lanes via shfl)
        #pragma unroll
        for (int ii = 0; ii < 4; ii++) {
            int gi = q0 + ty * 4 + ii;
            #pragma unroll
            for (int jj = 0; jj < 4; jj++) {
                int gj = j0 + tx * 4 + jj;
                if (gj > gi || gj <= gi - WIN) s4[ii][jj] = -1e30f;
            }
            float rmax = fmaxf(fmaxf(s4[ii][0], s4[ii][1]), fmaxf(s4[ii][2], s4[ii][3]));
            #pragma unroll
            for (int off = 8; off >= 1; off >>= 1)
                rmax = fmaxf(rmax, __shfl_xor_sync(0xffffffffu, rmax, off));
            float mn = fmaxf(m[ii], rmax);
            float sc = __expf(m[ii] - mn);
            float rs = 0.0f;
            #pragma unroll
            for (int jj = 0; jj < 4; jj++) {
                float p = __expf(s4[ii][jj] - mn);
                s4[ii][jj] = p;
                rs += p;
            }
            #pragma unroll
            for (int off = 8; off >= 1; off >>= 1)
                rs += __shfl_xor_sync(0xffffffffu, rs, off);
            l[ii] = l[ii] * sc + rs;
            m[ii] = mn;
            #pragma unroll
            for (int d = 0; d < 8; d++) o[ii][d] *= sc;
            *(float4*)&Ss[(ty * 4 + ii) * 64 + tx * 4] = *(float4*)s4[ii];
        }
        __syncthreads();

        // PV: o[ii][0..7] += sum_j P[row][j] * V[j][tx*8..tx*8+7]
        #pragma unroll 4
        for (int j = 0; j < 64; j++) {
            float4 v0 = *(const float4*)&Vs[j * 128 + tx * 8];
            float4 v1 = *(const float4*)&Vs[j * 128 + tx * 8 + 4];
            #pragma unroll
            for (int ii = 0; ii < 4; ii++) {
                float p = Ss[(ty * 4 + ii) * 64 + j];
                o[ii][0] = fmaf(p, v0.x, o[ii][0]);
                o[ii][1] = fmaf(p, v0.y, o[ii][1]);
                o[ii][2] = fmaf(p, v0.z, o[ii][2]);
                o[ii][3] = fmaf(p, v0.w, o[ii][3]);
                o[ii][4] = fmaf(p, v1.x, o[ii][4]);
                o[ii][5] = fmaf(p, v1.y, o[ii][5]);
                o[ii][6] = fmaf(p, v1.z, o[ii][6]);
                o[ii][7] = fmaf(p, v1.w, o[ii][7]);
            }
        }
    }

    // Normalize and write [s][h*128 + d]
    #pragma unroll
    for (int ii = 0; ii < 4; ii++) {
        float inv = 1.0f / l[ii];
        float* op = out + (size_t)(q0 + ty * 4 + ii) * (NH * DH) + h * DH + tx * 8;
        float4 r0, r1;
        r0.x = o[ii][0] * inv; r0.y = o[ii][1] * inv;
        r0.z = o[ii][2] * inv; r0.w = o[ii][3] * inv;
        r1.x = o[ii][4] * inv; r1.y = o[ii][5] * inv;
        r1.z = o[ii][6] * inv; r1.w = o[ii][7] * inv;
        *(float4*)(op)     = r0;
        *(float4*)(op + 4) = r1;
    }
}

// ---------------------------------------------------------------------------
// Launch: QKV GEMMs -> RoPE(q,k) -> attention -> O GEMM
// Inputs (metadata order): positions, hidden_states, Wq, bq, Wk, bk, Wv, bv, Wo, sink
// ---------------------------------------------------------------------------
extern "C" void kernel_launch(void* const* d_in, const int* in_sizes, int n_in,
                              void* d_out, int out_size)
{
    const int*   positions = (const int*)  d_in[0];
    const float* hidden    = (const float*)d_in[1];
    const float* Wq        = (const float*)d_in[2];
    const float* bq        = (const float*)d_in[3];
    const float* Wk        = (const float*)d_in[4];
    const float* bk        = (const float*)d_in[5];
    const float* Wv        = (const float*)d_in[6];
    const float* bv        = (const float*)d_in[7];
    const float* Wo        = (const float*)d_in[8];
    const float* sink      = (const float*)d_in[9];
    float* out = (float*)d_out;

    float *qp, *kp, *vp, *ap;
    cudaGetSymbolAddress((void**)&qp, g_q);
    cudaGetSymbolAddress((void**)&kp, g_k);
    cudaGetSymbolAddress((void**)&vp, g_v);
    cudaGetSymbolAddress((void**)&ap, g_attn);

    dim3 blk(256);

    // QKV projections
    sgemm_bias<<<dim3(HID / 128, S_LEN / 128), blk>>>(hidden, Wq, bq, qp, S_LEN, HID, HID);
    sgemm_bias<<<dim3((NKV * DH) / 128, S_LEN / 128), blk>>>(hidden, Wk, bk, kp, S_LEN, NKV * DH, HID);
    sgemm_bias<<<dim3((NKV * DH) / 128, S_LEN / 128), blk>>>(hidden, Wv, bv, vp, S_LEN, NKV * DH, HID);

    // RoPE on q and k
    rope_kernel<<<(S_LEN * NH  * 64 + 255) / 256, 256>>>(qp, positions, NH);
    rope_kernel<<<(S_LEN * NKV * 64 + 255) / 256, 256>>>(kp, positions, NKV);

    // Attention
    int smem_bytes = ATTN_SMEM_FLOATS * (int)sizeof(float);  // 114688
    cudaFuncSetAttribute(attn_kernel, cudaFuncAttributeMaxDynamicSharedMemorySize, smem_bytes);
    attn_kernel<<<dim3(S_LEN / 64, NH), blk, smem_bytes>>>(qp, kp, vp, sink, ap);

    // Output projection (no bias)
    sgemm_bias<<<dim3(HID / 128, S_LEN / 128), blk>>>(ap, Wo, nullptr, out, S_LEN, HID, HID);
}